// round 15
// baseline (speedup 1.0000x reference)
#include <cuda_runtime.h>
#include <cuda_fp16.h>
#include <cstdint>
#include <math.h>

#define N_NODES  100000
#define N_EDGES  3200000
#define N_GRAPHS 1024
#define F        128
#define CAP      128          // padded bucket capacity per node (degree ~ 32 +/- 5.7)

// ---------------- scratch (device globals; no allocation allowed) ----------
__device__ __half g_xhA[(size_t)N_NODES * F];
__device__ __half g_xhB[(size_t)N_NODES * F];
__device__ __half g_aggh[(size_t)N_NODES * F];
__device__ int   g_cursor[N_NODES];
__device__ int   g_ssrc[(size_t)N_NODES * CAP];
__device__ float g_pool[N_GRAPHS * F];
// f16 image of W, stored as Bt[n][k] (n-major): [layer][128n x 128k]
__device__ __half g_Wimg[3][16384];

// ============================ PTX helpers ===================================
__device__ __forceinline__ uint32_t smem_u32(const void* p) {
    uint32_t a;
    asm("{ .reg .u64 t; cvta.to.shared.u64 t, %1; cvt.u32.u64 %0, t; }"
        : "=r"(a) : "l"(p));
    return a;
}

__device__ __forceinline__ void ldsm4(uint32_t* r, uint32_t p) {
    asm volatile("ldmatrix.sync.aligned.m8n8.x4.shared.b16 {%0,%1,%2,%3}, [%4];"
        : "=r"(r[0]), "=r"(r[1]), "=r"(r[2]), "=r"(r[3]) : "r"(p));
}

__device__ __forceinline__ void mma16816h(float* d, const uint32_t* a, const uint32_t* b) {
    asm volatile(
        "mma.sync.aligned.m16n8k16.row.col.f32.f16.f16.f32 "
        "{%0,%1,%2,%3}, {%4,%5,%6,%7}, {%8,%9}, {%0,%1,%2,%3};"
        : "+f"(d[0]), "+f"(d[1]), "+f"(d[2]), "+f"(d[3])
        : "r"(a[0]), "r"(a[1]), "r"(a[2]), "r"(a[3]), "r"(b[0]), "r"(b[1]));
}

// ------ fused preprocessing: cursors, pool zero, x->fp16, W->f16 Bt image ---
__global__ void pre_kernel(const float* __restrict__ x, const float* __restrict__ Wc) {
    int i = blockIdx.x * blockDim.x + threadIdx.x;
    if (i < N_NODES * 32) {
        float4 v = __ldg(&((const float4*)x)[i]);
        __half2 a = __floats2half2_rn(v.x, v.y);
        __half2 b = __floats2half2_rn(v.z, v.w);
        uint2 o;
        o.x = *(uint32_t*)&a;
        o.y = *(uint32_t*)&b;
        ((uint2*)g_xhA)[i] = o;
    }
    if (i < N_NODES) g_cursor[i] = i * CAP;
    if (i < N_GRAPHS * F) g_pool[i] = 0.0f;
    if (i < 3 * 16384) {
        int L = i >> 14;
        int e = i & 16383;
        int k = e >> 7;           // 0..127 (input dim)
        int n = e & 127;          // 0..127 (output dim)
        float w = Wc[(size_t)L * 16384 + k * 128 + n];
        g_Wimg[L][n * 128 + k] = __float2half_rn(w);   // Bt[n][k]
    }
}

// ---------------- scatter edges into padded buckets --------------------------
__global__ void scatter_kernel(const int* __restrict__ src, const int* __restrict__ dst) {
    int i = blockIdx.x * blockDim.x + threadIdx.x;   // over N_EDGES/4
    if (i >= N_EDGES / 4) return;
    int4 s = __ldg(&((const int4*)src)[i]);
    int4 d = __ldg(&((const int4*)dst)[i]);
    g_ssrc[atomicAdd(&g_cursor[d.x], 1)] = s.x;
    g_ssrc[atomicAdd(&g_cursor[d.y], 1)] = s.y;
    g_ssrc[atomicAdd(&g_cursor[d.z], 1)] = s.z;
    g_ssrc[atomicAdd(&g_cursor[d.w], 1)] = s.w;
}

// ------- aggregation: warp per node, fp16 gather, fp32 accum -> fp16 out ----
__global__ void agg_kernel(const __half* __restrict__ xin) {
    int warp = (blockIdx.x * blockDim.x + threadIdx.x) >> 5;
    int lane = threadIdx.x & 31;
    if (warp >= N_NODES) return;
    int beg = warp * CAP;
    int end = __ldg(&g_cursor[warp]);
    const uint2* xv = (const uint2*)xin;    // 8B = 4 halfs per lane
    float4 acc = make_float4(0.f, 0.f, 0.f, 0.f);
    int e = beg;
    int n4 = beg + ((end - beg) & ~3);
    for (; e < n4; e += 4) {
        int s0 = __ldg(&g_ssrc[e + 0]);
        int s1 = __ldg(&g_ssrc[e + 1]);
        int s2 = __ldg(&g_ssrc[e + 2]);
        int s3 = __ldg(&g_ssrc[e + 3]);
        uint2 h0 = __ldg(&xv[(size_t)s0 * 32 + lane]);
        uint2 h1 = __ldg(&xv[(size_t)s1 * 32 + lane]);
        uint2 h2 = __ldg(&xv[(size_t)s2 * 32 + lane]);
        uint2 h3 = __ldg(&xv[(size_t)s3 * 32 + lane]);
        float2 a0 = __half22float2(*(__half2*)&h0.x);
        float2 b0 = __half22float2(*(__half2*)&h0.y);
        float2 a1 = __half22float2(*(__half2*)&h1.x);
        float2 b1 = __half22float2(*(__half2*)&h1.y);
        float2 a2 = __half22float2(*(__half2*)&h2.x);
        float2 b2 = __half22float2(*(__half2*)&h2.y);
        float2 a3 = __half22float2(*(__half2*)&h3.x);
        float2 b3 = __half22float2(*(__half2*)&h3.y);
        acc.x += a0.x + a1.x + a2.x + a3.x;
        acc.y += a0.y + a1.y + a2.y + a3.y;
        acc.z += b0.x + b1.x + b2.x + b3.x;
        acc.w += b0.y + b1.y + b2.y + b3.y;
    }
    for (; e < end; e++) {
        int s = __ldg(&g_ssrc[e]);
        uint2 h = __ldg(&xv[(size_t)s * 32 + lane]);
        float2 a = __half22float2(*(__half2*)&h.x);
        float2 b = __half22float2(*(__half2*)&h.y);
        acc.x += a.x; acc.y += a.y; acc.z += b.x; acc.w += b.y;
    }
    __half2 o01 = __floats2half2_rn(acc.x, acc.y);
    __half2 o23 = __floats2half2_rn(acc.z, acc.w);
    uint2 o;
    o.x = *(uint32_t*)&o01;
    o.y = *(uint32_t*)&o23;
    ((uint2*)g_aggh)[(size_t)warp * 32 + lane] = o;
}

// ---- persistent GEMM via mma.sync f16: xout = relu(aggh @ W + b) -----------
// CTA tile: 128 rows x 128 cols, K=128. Warp grid 4m x 2n, warp tile m32 x n64.
// Persistent: W loaded once/CTA; A double-buffered with register prefetch.
// smem: W [128][136] + 2x A [128][136] f16 -> 104448 B => 2 CTAs/SM
#define ASTRIDE 136
#define GEMM_SMEM (3 * 128 * ASTRIDE * 2)
#define GEMM_GRID 304          // 2 CTAs x 152 SMs
#define NTILES    ((N_NODES + 127) / 128)

__global__ __launch_bounds__(256, 2)
void gemm_mma(const __half* __restrict__ wimg,   // [128][128] Bt (f16)
              const float* __restrict__ bias,
              __half* __restrict__ xout, int M) {
    extern __shared__ __align__(16) char smem[];
    __half* sW  = (__half*)smem;
    __half* sA0 = sW + 128 * ASTRIDE;
    __half* sA1 = sA0 + 128 * ASTRIDE;
    int tid = threadIdx.x;
    int warp = tid >> 5;
    int lane = tid & 31;

    const uint4* wsrc = (const uint4*)wimg;   // 16 uint4 per Bt row
    const uint4* asrc = (const uint4*)g_aggh; // 16 uint4 per A row

    // load W once + first A tile into sA0
    int tile = blockIdx.x;
    {
#pragma unroll
        for (int j = 0; j < 8; j++) {
            int i = tid + j * 256;
            int r = i >> 4, kq = i & 15;
            *(uint4*)&sW[r * ASTRIDE + kq * 8] = __ldg(&wsrc[i]);
            if (tile < NTILES) {
                long rr = (long)tile * 128 + r;
                uint4 av = make_uint4(0u, 0u, 0u, 0u);
                if (rr < M) av = __ldg(&asrc[rr * 16 + kq]);
                *(uint4*)&sA0[r * ASTRIDE + kq * 8] = av;
            }
        }
    }
    __syncthreads();

    // warp tile: m32 (2 m-frags) x n64 (8 n8-tiles)
    int wm = warp >> 1;        // 0..3
    int wn = warp & 1;         // 0..1
    int m0 = wm * 32;
    int nb = wn * 64;

    uint32_t a_off = (uint32_t)(((m0 + (lane & 15)) * ASTRIDE + ((lane >> 4) * 8)) * 2);
    uint32_t b_off = (uint32_t)(((nb + (lane & 7) + ((lane >> 4) << 3)) * ASTRIDE +
                                 (((lane >> 3) & 1) * 8)) * 2);
    uint32_t bbase = smem_u32(sW) + b_off;
    int cbase = 2 * (lane & 3);

    int buf = 0;
    for (; tile < NTILES; tile += GEMM_GRID) {
        long row0 = (long)tile * 128;
        int next = tile + GEMM_GRID;
        bool hasNext = (next < NTILES);

        // issue prefetch LDGs for the next tile (hidden under MMA+epilogue)
        uint4 pf[8];
        if (hasNext) {
            long nrow0 = (long)next * 128;
#pragma unroll
            for (int j = 0; j < 8; j++) {
                int i = tid + j * 256;
                int r = i >> 4, kq = i & 15;
                long rr = nrow0 + r;
                pf[j] = (rr < M) ? __ldg(&asrc[rr * 16 + kq])
                                 : make_uint4(0u, 0u, 0u, 0u);
            }
        }

        float acc[2][8][4];
#pragma unroll
        for (int mi = 0; mi < 2; mi++)
#pragma unroll
            for (int t = 0; t < 8; t++)
#pragma unroll
                for (int j = 0; j < 4; j++) acc[mi][t][j] = 0.f;

        uint32_t abase = smem_u32(buf ? sA1 : sA0) + a_off;
#pragma unroll
        for (int kt = 0; kt < 8; kt++) {
            uint32_t a0[4], a1[4];
            ldsm4(a0, abase + kt * 32);
            ldsm4(a1, abase + (uint32_t)(16 * ASTRIDE * 2) + kt * 32);
#pragma unroll
            for (int np = 0; np < 4; np++) {
                uint32_t b[4];
                ldsm4(b, bbase + (uint32_t)(np * 16 * ASTRIDE * 2) + kt * 32);
                mma16816h(acc[0][2 * np],     a0, b);
                mma16816h(acc[0][2 * np + 1], a0, b + 2);
                mma16816h(acc[1][2 * np],     a1, b);
                mma16816h(acc[1][2 * np + 1], a1, b + 2);
            }
        }

        // epilogue: bias + relu -> fp16 out
#pragma unroll
        for (int mi = 0; mi < 2; mi++) {
            int r_lo = m0 + mi * 16 + (lane >> 2);
#pragma unroll
            for (int t = 0; t < 8; t++) {
                int col = nb + t * 8 + cbase;
                float b0 = __ldg(&bias[col]);
                float b1 = __ldg(&bias[col + 1]);
                if (row0 + r_lo < M) {
                    __half2 o = __floats2half2_rn(fmaxf(acc[mi][t][0] + b0, 0.f),
                                                  fmaxf(acc[mi][t][1] + b1, 0.f));
                    *(__half2*)&xout[(row0 + r_lo) * 128 + col] = o;
                }
                if (row0 + r_lo + 8 < M) {
                    __half2 o = __floats2half2_rn(fmaxf(acc[mi][t][2] + b0, 0.f),
                                                  fmaxf(acc[mi][t][3] + b1, 0.f));
                    *(__half2*)&xout[(row0 + r_lo + 8) * 128 + col] = o;
                }
            }
        }

        __syncthreads();   // all warps done reading sA[buf] (and prior STS target)
        if (hasNext) {
            __half* sAn = buf ? sA0 : sA1;
#pragma unroll
            for (int j = 0; j < 8; j++) {
                int i = tid + j * 256;
                int r = i >> 4, kq = i & 15;
                *(uint4*)&sAn[r * ASTRIDE + kq * 8] = pf[j];
            }
        }
        __syncthreads();   // STS visible before next iteration's ldsm
        buf ^= 1;
    }
}

// ---------------- global sum pool: sorted-run segmented reduction -----------
__global__ void pool_kernel(const __half* __restrict__ x, const int* __restrict__ batching) {
    int i = blockIdx.x * blockDim.x + threadIdx.x;
    int chunk = i >> 5;
    int q = i & 31;
    int n0 = chunk * 64;
    if (n0 >= N_NODES) return;
    int n1 = n0 + 64;
    if (n1 > N_NODES) n1 = N_NODES;
    const uint2* xv = (const uint2*)x;
    int curb = __ldg(&batching[n0]);
    float4 acc = make_float4(0.f, 0.f, 0.f, 0.f);
    for (int n = n0; n < n1; n++) {
        int b = __ldg(&batching[n]);
        if (b != curb) {
            float* dp = &g_pool[curb * F + q * 4];
            atomicAdd(dp + 0, acc.x); atomicAdd(dp + 1, acc.y);
            atomicAdd(dp + 2, acc.z); atomicAdd(dp + 3, acc.w);
            curb = b;
            acc = make_float4(0.f, 0.f, 0.f, 0.f);
        }
        uint2 h = __ldg(&xv[(size_t)n * 32 + q]);
        float2 a = __half22float2(*(__half2*)&h.x);
        float2 b2 = __half22float2(*(__half2*)&h.y);
        acc.x += a.x; acc.y += a.y; acc.z += b2.x; acc.w += b2.y;
    }
    float* dp = &g_pool[curb * F + q * 4];
    atomicAdd(dp + 0, acc.x); atomicAdd(dp + 1, acc.y);
    atomicAdd(dp + 2, acc.z); atomicAdd(dp + 3, acc.w);
}

// ---------------- head: FC1 -> FC2 -> softmax --------------------------------
__global__ void head_kernel(const float* __restrict__ Wf1, const float* __restrict__ bf1,
                            const float* __restrict__ Wf2, const float* __restrict__ bf2,
                            float* __restrict__ out) {
    __shared__ float gs[128];
    __shared__ float hs[64];
    __shared__ float logits[10];
    int g = blockIdx.x, tid = threadIdx.x;
    gs[tid] = g_pool[g * F + tid];
    __syncthreads();
    if (tid < 64) {
        float s = __ldg(&bf1[tid]);
#pragma unroll 8
        for (int k = 0; k < 128; k++)
            s = fmaf(gs[k], __ldg(&Wf1[k * 64 + tid]), s);
        hs[tid] = s;
    }
    __syncthreads();
    if (tid < 10) {
        float s = __ldg(&bf2[tid]);
#pragma unroll 8
        for (int k = 0; k < 64; k++)
            s = fmaf(hs[k], __ldg(&Wf2[k * 10 + tid]), s);
        logits[tid] = s;
    }
    __syncthreads();
    if (tid == 0) {
        float m = logits[0];
#pragma unroll
        for (int i = 1; i < 10; i++) m = fmaxf(m, logits[i]);
        float e[10], sum = 0.f;
#pragma unroll
        for (int i = 0; i < 10; i++) { e[i] = expf(logits[i] - m); sum += e[i]; }
        float inv = 1.0f / sum;
#pragma unroll
        for (int i = 0; i < 10; i++) out[g * 10 + i] = e[i] * inv;
    }
}

// ---------------- launch ----------------------------------------------------
extern "C" void kernel_launch(void* const* d_in, const int* in_sizes, int n_in,
                              void* d_out, int out_size) {
    const float* node_attr = (const float*)d_in[0];
    const float* Wc        = (const float*)d_in[1];
    const float* bc        = (const float*)d_in[2];
    const float* Wf1       = (const float*)d_in[3];
    const float* bf1       = (const float*)d_in[4];
    const float* Wf2       = (const float*)d_in[5];
    const float* bf2       = (const float*)d_in[6];
    const int*   src       = (const int*)d_in[7];
    const int*   dst       = (const int*)d_in[8];
    const int*   batching  = (const int*)d_in[9];
    float* out = (float*)d_out;

    __half *xhA, *xhB;
    cudaGetSymbolAddress((void**)&xhA, g_xhA);
    cudaGetSymbolAddress((void**)&xhB, g_xhB);
    __half* wimg;
    cudaGetSymbolAddress((void**)&wimg, g_Wimg);

    cudaFuncSetAttribute((const void*)gemm_mma,
                         cudaFuncAttributeMaxDynamicSharedMemorySize, GEMM_SMEM);

    // fused preprocessing (cursors, pool zero, fp16 convert, W image) + scatter
    pre_kernel<<<(N_NODES * 32 + 255) / 256, 256>>>(node_attr, Wc);
    scatter_kernel<<<(N_EDGES / 4 + 255) / 256, 256>>>(src, dst);

    // three conv layers: agg (fp16 in/out, fp32 accum) -> persistent mma GEMM
    const int agg_blocks = (N_NODES * 32 + 255) / 256;

    agg_kernel<<<agg_blocks, 256>>>(xhA);
    gemm_mma<<<GEMM_GRID, 256, GEMM_SMEM>>>(wimg,         bc,         xhB, N_NODES);
    agg_kernel<<<agg_blocks, 256>>>(xhB);
    gemm_mma<<<GEMM_GRID, 256, GEMM_SMEM>>>(wimg + 16384, bc + F,     xhA, N_NODES);
    agg_kernel<<<agg_blocks, 256>>>(xhA);
    gemm_mma<<<GEMM_GRID, 256, GEMM_SMEM>>>(wimg + 32768, bc + 2 * F, xhB, N_NODES);

    pool_kernel<<<((N_NODES + 63) / 64 * 32 + 255) / 256, 256>>>(xhB, batching);
    head_kernel<<<N_GRAPHS, 128>>>(Wf1, bf1, Wf2, bf2, out);
}

// round 16
// speedup vs baseline: 1.0060x; 1.0060x over previous
#include <cuda_runtime.h>
#include <cuda_fp16.h>
#include <cstdint>
#include <math.h>

#define N_NODES  100000
#define N_EDGES  3200000
#define N_GRAPHS 1024
#define F        128
#define CAP      128          // padded bucket capacity per node (degree ~ 32 +/- 5.7)

// ---------------- scratch (device globals; no allocation allowed) ----------
__device__ __half g_xhA[(size_t)N_NODES * F];
__device__ __half g_xhB[(size_t)N_NODES * F];
__device__ __half g_aggh[(size_t)N_NODES * F];
__device__ int   g_cursor[N_NODES];
__device__ int   g_ssrc[(size_t)N_NODES * CAP];
__device__ float g_pool[N_GRAPHS * F];
// f16 image of W, stored as Bt[n][k] (n-major): [layer][128n x 128k]
__device__ __half g_Wimg[3][16384];

// ============================ PTX helpers ===================================
__device__ __forceinline__ uint32_t smem_u32(const void* p) {
    uint32_t a;
    asm("{ .reg .u64 t; cvta.to.shared.u64 t, %1; cvt.u32.u64 %0, t; }"
        : "=r"(a) : "l"(p));
    return a;
}

__device__ __forceinline__ void ldsm4(uint32_t* r, uint32_t p) {
    asm volatile("ldmatrix.sync.aligned.m8n8.x4.shared.b16 {%0,%1,%2,%3}, [%4];"
        : "=r"(r[0]), "=r"(r[1]), "=r"(r[2]), "=r"(r[3]) : "r"(p));
}

__device__ __forceinline__ void mma16816h(float* d, const uint32_t* a, const uint32_t* b) {
    asm volatile(
        "mma.sync.aligned.m16n8k16.row.col.f32.f16.f16.f32 "
        "{%0,%1,%2,%3}, {%4,%5,%6,%7}, {%8,%9}, {%0,%1,%2,%3};"
        : "+f"(d[0]), "+f"(d[1]), "+f"(d[2]), "+f"(d[3])
        : "r"(a[0]), "r"(a[1]), "r"(a[2]), "r"(a[3]), "r"(b[0]), "r"(b[1]));
}

// ---------------- init: bucket cursors + pool (must precede scatter) --------
__global__ void init_kernel() {
    int i = blockIdx.x * blockDim.x + threadIdx.x;
    if (i < N_NODES) g_cursor[i] = i * CAP;
    if (i < N_GRAPHS * F) g_pool[i] = 0.0f;
}

// ------ cvt + W image (independent of scatter; runs on forked stream) -------
__global__ void cvtw_kernel(const float* __restrict__ x, const float* __restrict__ Wc) {
    int i = blockIdx.x * blockDim.x + threadIdx.x;
    if (i < N_NODES * 32) {
        float4 v = __ldg(&((const float4*)x)[i]);
        __half2 a = __floats2half2_rn(v.x, v.y);
        __half2 b = __floats2half2_rn(v.z, v.w);
        uint2 o;
        o.x = *(uint32_t*)&a;
        o.y = *(uint32_t*)&b;
        ((uint2*)g_xhA)[i] = o;
    }
    if (i < 3 * 16384) {
        int L = i >> 14;
        int e = i & 16383;
        int k = e >> 7;           // 0..127 (input dim)
        int n = e & 127;          // 0..127 (output dim)
        float w = Wc[(size_t)L * 16384 + k * 128 + n];
        g_Wimg[L][n * 128 + k] = __float2half_rn(w);   // Bt[n][k]
    }
}

// ---------------- scatter edges into padded buckets --------------------------
__global__ void scatter_kernel(const int* __restrict__ src, const int* __restrict__ dst) {
    int i = blockIdx.x * blockDim.x + threadIdx.x;   // over N_EDGES/4
    if (i >= N_EDGES / 4) return;
    int4 s = __ldg(&((const int4*)src)[i]);
    int4 d = __ldg(&((const int4*)dst)[i]);
    g_ssrc[atomicAdd(&g_cursor[d.x], 1)] = s.x;
    g_ssrc[atomicAdd(&g_cursor[d.y], 1)] = s.y;
    g_ssrc[atomicAdd(&g_cursor[d.z], 1)] = s.z;
    g_ssrc[atomicAdd(&g_cursor[d.w], 1)] = s.w;
}

// ------- aggregation: warp per node, fp16 gather, fp32 accum -> fp16 out ----
__global__ void agg_kernel(const __half* __restrict__ xin) {
    int warp = (blockIdx.x * blockDim.x + threadIdx.x) >> 5;
    int lane = threadIdx.x & 31;
    if (warp >= N_NODES) return;
    int beg = warp * CAP;
    int end = __ldg(&g_cursor[warp]);
    const uint2* xv = (const uint2*)xin;    // 8B = 4 halfs per lane
    float4 acc = make_float4(0.f, 0.f, 0.f, 0.f);
    int e = beg;
    int n4 = beg + ((end - beg) & ~3);
    for (; e < n4; e += 4) {
        int s0 = __ldg(&g_ssrc[e + 0]);
        int s1 = __ldg(&g_ssrc[e + 1]);
        int s2 = __ldg(&g_ssrc[e + 2]);
        int s3 = __ldg(&g_ssrc[e + 3]);
        uint2 h0 = __ldg(&xv[(size_t)s0 * 32 + lane]);
        uint2 h1 = __ldg(&xv[(size_t)s1 * 32 + lane]);
        uint2 h2 = __ldg(&xv[(size_t)s2 * 32 + lane]);
        uint2 h3 = __ldg(&xv[(size_t)s3 * 32 + lane]);
        float2 a0 = __half22float2(*(__half2*)&h0.x);
        float2 b0 = __half22float2(*(__half2*)&h0.y);
        float2 a1 = __half22float2(*(__half2*)&h1.x);
        float2 b1 = __half22float2(*(__half2*)&h1.y);
        float2 a2 = __half22float2(*(__half2*)&h2.x);
        float2 b2 = __half22float2(*(__half2*)&h2.y);
        float2 a3 = __half22float2(*(__half2*)&h3.x);
        float2 b3 = __half22float2(*(__half2*)&h3.y);
        acc.x += a0.x + a1.x + a2.x + a3.x;
        acc.y += a0.y + a1.y + a2.y + a3.y;
        acc.z += b0.x + b1.x + b2.x + b3.x;
        acc.w += b0.y + b1.y + b2.y + b3.y;
    }
    for (; e < end; e++) {
        int s = __ldg(&g_ssrc[e]);
        uint2 h = __ldg(&xv[(size_t)s * 32 + lane]);
        float2 a = __half22float2(*(__half2*)&h.x);
        float2 b = __half22float2(*(__half2*)&h.y);
        acc.x += a.x; acc.y += a.y; acc.z += b.x; acc.w += b.y;
    }
    __half2 o01 = __floats2half2_rn(acc.x, acc.y);
    __half2 o23 = __floats2half2_rn(acc.z, acc.w);
    uint2 o;
    o.x = *(uint32_t*)&o01;
    o.y = *(uint32_t*)&o23;
    ((uint2*)g_aggh)[(size_t)warp * 32 + lane] = o;
}

// ---------------- GEMM via mma.sync f16: xout = relu(aggh @ W + b) ----------
// CTA tile: 128 rows x 128 cols, K=128. Warp grid 4m x 2n, warp tile m32 x n64.
// smem: A [128][136] f16, W [128][136] f16 -> 69632 B => 3 CTAs/SM
#define ASTRIDE 136
#define GEMM_SMEM (2 * 128 * ASTRIDE * 2)

__global__ __launch_bounds__(256, 3)
void gemm_mma(const __half* __restrict__ wimg,   // [128][128] Bt (f16)
              const float* __restrict__ bias,
              __half* __restrict__ xout, int M) {
    extern __shared__ __align__(16) char smem[];
    __half* sA = (__half*)smem;
    __half* sW = sA + 128 * ASTRIDE;
    int tid = threadIdx.x;
    int warp = tid >> 5;
    int lane = tid & 31;
    long row0 = (long)blockIdx.x * 128;

    // copy W image (128 Bt rows) + A tile (fp16) into padded smem
    {
        const uint4* wsrc = (const uint4*)wimg;   // 16 uint4 per Bt row
        const uint4* asrc = (const uint4*)g_aggh; // 16 uint4 per A row
#pragma unroll
        for (int i = tid; i < 2048; i += 256) {
            int r = i >> 4, kq = i & 15;
            *(uint4*)&sW[r * ASTRIDE + kq * 8] = __ldg(&wsrc[i]);
            uint4 av = make_uint4(0u, 0u, 0u, 0u);
            if (row0 + r < M) av = __ldg(&asrc[(row0 + r) * 16 + kq]);
            *(uint4*)&sA[r * ASTRIDE + kq * 8] = av;
        }
    }
    __syncthreads();

    // warp tile: m32 (2 m-frags) x n64 (8 n8-tiles)
    int wm = warp >> 1;        // 0..3
    int wn = warp & 1;         // 0..1
    int m0 = wm * 32;
    int nb = wn * 64;

    float acc[2][8][4];
#pragma unroll
    for (int mi = 0; mi < 2; mi++)
#pragma unroll
        for (int t = 0; t < 8; t++)
#pragma unroll
            for (int j = 0; j < 4; j++) acc[mi][t][j] = 0.f;

    uint32_t a_off = (uint32_t)(((m0 + (lane & 15)) * ASTRIDE + ((lane >> 4) * 8)) * 2);
    uint32_t b_off = (uint32_t)(((nb + (lane & 7) + ((lane >> 4) << 3)) * ASTRIDE +
                                 (((lane >> 3) & 1) * 8)) * 2);

    uint32_t abase = smem_u32(sA) + a_off;
    uint32_t bbase = smem_u32(sW) + b_off;
#pragma unroll
    for (int kt = 0; kt < 8; kt++) {
        uint32_t a0[4], a1[4];
        ldsm4(a0, abase + kt * 32);
        ldsm4(a1, abase + (uint32_t)(16 * ASTRIDE * 2) + kt * 32);
#pragma unroll
        for (int np = 0; np < 4; np++) {
            uint32_t b[4];
            ldsm4(b, bbase + (uint32_t)(np * 16 * ASTRIDE * 2) + kt * 32);
            mma16816h(acc[0][2 * np],     a0, b);
            mma16816h(acc[0][2 * np + 1], a0, b + 2);
            mma16816h(acc[1][2 * np],     a1, b);
            mma16816h(acc[1][2 * np + 1], a1, b + 2);
        }
    }

    // epilogue: bias + relu -> fp16 out
    int cbase = 2 * (lane & 3);
#pragma unroll
    for (int mi = 0; mi < 2; mi++) {
        int r_lo = m0 + mi * 16 + (lane >> 2);
#pragma unroll
        for (int t = 0; t < 8; t++) {
            int col = nb + t * 8 + cbase;
            float b0 = __ldg(&bias[col]);
            float b1 = __ldg(&bias[col + 1]);
            if (row0 + r_lo < M) {
                __half2 o = __floats2half2_rn(fmaxf(acc[mi][t][0] + b0, 0.f),
                                              fmaxf(acc[mi][t][1] + b1, 0.f));
                *(__half2*)&xout[(row0 + r_lo) * 128 + col] = o;
            }
            if (row0 + r_lo + 8 < M) {
                __half2 o = __floats2half2_rn(fmaxf(acc[mi][t][2] + b0, 0.f),
                                              fmaxf(acc[mi][t][3] + b1, 0.f));
                *(__half2*)&xout[(row0 + r_lo + 8) * 128 + col] = o;
            }
        }
    }
}

// ---------------- global sum pool: sorted-run segmented reduction -----------
__global__ void pool_kernel(const __half* __restrict__ x, const int* __restrict__ batching) {
    int i = blockIdx.x * blockDim.x + threadIdx.x;
    int chunk = i >> 5;
    int q = i & 31;
    int n0 = chunk * 64;
    if (n0 >= N_NODES) return;
    int n1 = n0 + 64;
    if (n1 > N_NODES) n1 = N_NODES;
    const uint2* xv = (const uint2*)x;
    int curb = __ldg(&batching[n0]);
    float4 acc = make_float4(0.f, 0.f, 0.f, 0.f);
    for (int n = n0; n < n1; n++) {
        int b = __ldg(&batching[n]);
        if (b != curb) {
            float* dp = &g_pool[curb * F + q * 4];
            atomicAdd(dp + 0, acc.x); atomicAdd(dp + 1, acc.y);
            atomicAdd(dp + 2, acc.z); atomicAdd(dp + 3, acc.w);
            curb = b;
            acc = make_float4(0.f, 0.f, 0.f, 0.f);
        }
        uint2 h = __ldg(&xv[(size_t)n * 32 + q]);
        float2 a = __half22float2(*(__half2*)&h.x);
        float2 b2 = __half22float2(*(__half2*)&h.y);
        acc.x += a.x; acc.y += a.y; acc.z += b2.x; acc.w += b2.y;
    }
    float* dp = &g_pool[curb * F + q * 4];
    atomicAdd(dp + 0, acc.x); atomicAdd(dp + 1, acc.y);
    atomicAdd(dp + 2, acc.z); atomicAdd(dp + 3, acc.w);
}

// ---------------- head: FC1 -> FC2 -> softmax --------------------------------
__global__ void head_kernel(const float* __restrict__ Wf1, const float* __restrict__ bf1,
                            const float* __restrict__ Wf2, const float* __restrict__ bf2,
                            float* __restrict__ out) {
    __shared__ float gs[128];
    __shared__ float hs[64];
    __shared__ float logits[10];
    int g = blockIdx.x, tid = threadIdx.x;
    gs[tid] = g_pool[g * F + tid];
    __syncthreads();
    if (tid < 64) {
        float s = __ldg(&bf1[tid]);
#pragma unroll 8
        for (int k = 0; k < 128; k++)
            s = fmaf(gs[k], __ldg(&Wf1[k * 64 + tid]), s);
        hs[tid] = s;
    }
    __syncthreads();
    if (tid < 10) {
        float s = __ldg(&bf2[tid]);
#pragma unroll 8
        for (int k = 0; k < 64; k++)
            s = fmaf(hs[k], __ldg(&Wf2[k * 10 + tid]), s);
        logits[tid] = s;
    }
    __syncthreads();
    if (tid == 0) {
        float m = logits[0];
#pragma unroll
        for (int i = 1; i < 10; i++) m = fmaxf(m, logits[i]);
        float e[10], sum = 0.f;
#pragma unroll
        for (int i = 0; i < 10; i++) { e[i] = expf(logits[i] - m); sum += e[i]; }
        float inv = 1.0f / sum;
#pragma unroll
        for (int i = 0; i < 10; i++) out[g * 10 + i] = e[i] * inv;
    }
}

// ---------------- launch ----------------------------------------------------
extern "C" void kernel_launch(void* const* d_in, const int* in_sizes, int n_in,
                              void* d_out, int out_size) {
    const float* node_attr = (const float*)d_in[0];
    const float* Wc        = (const float*)d_in[1];
    const float* bc        = (const float*)d_in[2];
    const float* Wf1       = (const float*)d_in[3];
    const float* bf1       = (const float*)d_in[4];
    const float* Wf2       = (const float*)d_in[5];
    const float* bf2       = (const float*)d_in[6];
    const int*   src       = (const int*)d_in[7];
    const int*   dst       = (const int*)d_in[8];
    const int*   batching  = (const int*)d_in[9];
    float* out = (float*)d_out;

    __half *xhA, *xhB;
    cudaGetSymbolAddress((void**)&xhA, g_xhA);
    cudaGetSymbolAddress((void**)&xhB, g_xhB);
    __half* wimg;
    cudaGetSymbolAddress((void**)&wimg, g_Wimg);

    cudaFuncSetAttribute((const void*)gemm_mma,
                         cudaFuncAttributeMaxDynamicSharedMemorySize, GEMM_SMEM);

    // fork a side stream: scatter (atomic-latency-bound) runs on the main
    // stream while cvt + W-image (bandwidth-bound) run concurrently.
    cudaStream_t s2;
    cudaStreamCreateWithFlags(&s2, cudaStreamNonBlocking);
    cudaEvent_t evFork, evJoin;
    cudaEventCreateWithFlags(&evFork, cudaEventDisableTiming);
    cudaEventCreateWithFlags(&evJoin, cudaEventDisableTiming);

    init_kernel<<<(N_GRAPHS * F + 255) / 256, 256>>>();   // cursors + pool
    cudaEventRecord(evFork, 0);
    cudaStreamWaitEvent(s2, evFork, 0);
    cvtw_kernel<<<(N_NODES * 32 + 255) / 256, 256, 0, s2>>>(node_attr, Wc);
    scatter_kernel<<<(N_EDGES / 4 + 255) / 256, 256>>>(src, dst);
    cudaEventRecord(evJoin, s2);
    cudaStreamWaitEvent(0, evJoin, 0);

    // three conv layers: agg (fp16 in/out, fp32 accum) -> mma GEMM -> fp16
    const int agg_blocks  = (N_NODES * 32 + 255) / 256;
    const int gemm_blocks = (N_NODES + 127) / 128;

    agg_kernel<<<agg_blocks, 256>>>(xhA);
    gemm_mma<<<gemm_blocks, 256, GEMM_SMEM>>>(wimg,         bc,         xhB, N_NODES);
    agg_kernel<<<agg_blocks, 256>>>(xhB);
    gemm_mma<<<gemm_blocks, 256, GEMM_SMEM>>>(wimg + 16384, bc + F,     xhA, N_NODES);
    agg_kernel<<<agg_blocks, 256>>>(xhA);
    gemm_mma<<<gemm_blocks, 256, GEMM_SMEM>>>(wimg + 32768, bc + 2 * F, xhB, N_NODES);

    pool_kernel<<<((N_NODES + 63) / 64 * 32 + 255) / 256, 256>>>(xhB, batching);
    head_kernel<<<N_GRAPHS, 128>>>(Wf1, bf1, Wf2, bf2, out);

    cudaEventDestroy(evFork);
    cudaEventDestroy(evJoin);
    cudaStreamDestroy(s2);
}